// round 16
// baseline (speedup 1.0000x reference)
#include <cuda_runtime.h>
#include <cuda_fp16.h>
#include <cstdint>
#include <math.h>

// Shapes (fixed)
#define NB 128
#define NN 256
#define NC 512
#define NH 16
#define HD 32
#define QSCALE 0.17677669529663687f  // 1/sqrt(32)
#define LOG2E  1.4426950408889634f

// GEMM tiling (fp16 k16), 256 threads, 8 warps (2x4), warp tile 64x32
#define BM 128
#define BN 128
#define BK 32
#define KH 40
#define CHUNK_HALFS (BM * KH)
#define STAGES 3
#define GEMM_SMEM (STAGES * 2 * CHUNK_HALFS * 2)   // 61440 B

// Attention smem (halves)
#define KS_ST 40
#define VS_ST 264
#define ATT_SMEM ((NN * KS_ST + HD * VS_ST) * 2)   // 37376 B

// Scratch (device globals — no allocation allowed)
__device__ __half g_Qh[(size_t)NB * NH * NN * HD];  // fp16, scaled QSCALE*LOG2E
__device__ __half g_Kh[(size_t)NB * NH * NN * HD];  // [bh][key][dim]
__device__ __half g_Vh[(size_t)NB * NH * NN * HD];  // [bh][dim][key]
__device__ __half g_biasTh[(size_t)NH * NN * NN];   // [h][query][key], * LOG2E, fp16
__device__ __half g_AOh[(size_t)NB * NN * NC];      // attention out, fp16
__device__ __half g_Xh [(size_t)NB * NN * NC];
__device__ __half g_Wqh[(size_t)3 * NC * NC];
__device__ __half g_Wph[(size_t)NC * NC];

__device__ __forceinline__ uint32_t ph2(float a, float b) {
    __half2 h = __floats2half2_rn(a, b);
    return *(uint32_t*)&h;
}
__device__ __forceinline__ void mma_f16(float* d, const uint32_t* a, const uint32_t* b) {
    asm volatile(
        "mma.sync.aligned.m16n8k16.row.col.f32.f16.f16.f32 "
        "{%0,%1,%2,%3}, {%4,%5,%6,%7}, {%8,%9}, {%0,%1,%2,%3};"
        : "+f"(d[0]), "+f"(d[1]), "+f"(d[2]), "+f"(d[3])
        : "r"(a[0]), "r"(a[1]), "r"(a[2]), "r"(a[3]), "r"(b[0]), "r"(b[1]));
}
#define LDSM_X4(r0, r1, r2, r3, addr)                                         \
    asm volatile("ldmatrix.sync.aligned.m8n8.x4.shared.b16 {%0,%1,%2,%3}, [%4];" \
                 : "=r"(r0), "=r"(r1), "=r"(r2), "=r"(r3) : "r"(addr))
#define CP16(dst_u32, src_ptr)                                                \
    asm volatile("cp.async.cg.shared.global [%0], [%1], 16;"                  \
                 :: "r"(dst_u32), "l"(src_ptr))
#define CP_COMMIT() asm volatile("cp.async.commit_group;")
#define CP_WAIT1()  asm volatile("cp.async.wait_group 1;" ::: "memory")

// ---------------------------------------------------------------------------
// Fused fp32->fp16 convert for the three input arrays (one launch)
// ---------------------------------------------------------------------------
#define XN4   (NB * NN * NC / 4)
#define WQN4  (3 * NC * NC / 4)
#define WPN4  (NC * NC / 4)
__global__ void f2h3_kernel(const float4* __restrict__ sx,
                            const float4* __restrict__ swq,
                            const float4* __restrict__ swp) {
    int i = blockIdx.x * blockDim.x + threadIdx.x;
    const float4* src;
    uint2* dst;
    int j;
    if (i < XN4) {
        src = sx; dst = (uint2*)g_Xh; j = i;
    } else if (i < XN4 + WQN4) {
        src = swq; dst = (uint2*)g_Wqh; j = i - XN4;
    } else if (i < XN4 + WQN4 + WPN4) {
        src = swp; dst = (uint2*)g_Wph; j = i - XN4 - WQN4;
    } else {
        return;
    }
    float4 f = src[j];
    dst[j] = make_uint2(ph2(f.x, f.y), ph2(f.z, f.w));
}

__global__ void bias_kernel(const float* __restrict__ rpb) {
    int idx = blockIdx.x * blockDim.x + threadIdx.x;
    int n = idx & 255;          // key
    int m = (idx >> 8) & 255;   // query
    int h = idx >> 16;
    int t = ((m >> 5) - (n >> 5) + 7) * 63 + ((m & 31) - (n & 31) + 31);
    g_biasTh[idx] = __float2half_rn(rpb[t * NH + h] * LOG2E);
}

// ---------------------------------------------------------------------------
// fp16 GEMM: cp.async 3-stage + ldmatrix (unchanged from R14/R15).
// ---------------------------------------------------------------------------
__global__ __launch_bounds__(256, 2) void mma_gemm(const __half* __restrict__ A,
                                                   const __half* __restrict__ W,
                                                   const float* __restrict__ bias,
                                                   int mode, float* __restrict__ out) {
    extern __shared__ __half smh[];
    int tid = threadIdx.x;
    int wid = tid >> 5;
    int lane = tid & 31;
    int wr = wid >> 2;
    int wc = wid & 3;
    int lr = lane >> 2;
    int lc = lane & 3;

    int row0 = blockIdx.y * BM;
    int col0 = blockIdx.x * BN;
    uint32_t smbase = (uint32_t)__cvta_generic_to_shared(smh);

    int rA = tid >> 2, sg = tid & 3;
    const __half* gA = A + (size_t)(row0 + rA) * NC + sg * 8;
    const __half* gW = W + (size_t)(col0 + rA) * NC + sg * 8;
    uint32_t dA0 = (uint32_t)((rA * KH + sg * 8) * 2);
    uint32_t dA1 = (uint32_t)(((rA + 64) * KH + sg * 8) * 2);

    float acc[4][4][4];
#pragma unroll
    for (int i = 0; i < 4; i++)
#pragma unroll
        for (int j = 0; j < 4; j++)
#pragma unroll
            for (int k = 0; k < 4; k++) acc[i][j][k] = 0.0f;

    const int NCH = NC / BK;  // 16
#pragma unroll
    for (int c = 0; c < 2; c++) {
        uint32_t ab = smbase + (uint32_t)(c * 2 * CHUNK_HALFS) * 2;
        uint32_t bb = ab + CHUNK_HALFS * 2;
        CP16(ab + dA0, gA + c * BK);
        CP16(ab + dA1, gA + (size_t)64 * NC + c * BK);
        CP16(bb + dA0, gW + c * BK);
        CP16(bb + dA1, gW + (size_t)64 * NC + c * BK);
        CP_COMMIT();
    }

    int a_row = (lane & 15);
    int a_col = (lane >> 4) * 8;
    int b_row = ((lane >> 4) << 3) + (lane & 7);
    int b_col = ((lane >> 3) & 1) * 8;

#pragma unroll 1
    for (int c = 0; c < NCH; c++) {
        CP_WAIT1();
        __syncthreads();
        if (c + 2 < NCH) {
            int st = (c + 2) % 3;
            uint32_t ab = smbase + (uint32_t)(st * 2 * CHUNK_HALFS) * 2;
            uint32_t bb = ab + CHUNK_HALFS * 2;
            int k0 = (c + 2) * BK;
            CP16(ab + dA0, gA + k0);
            CP16(ab + dA1, gA + (size_t)64 * NC + k0);
            CP16(bb + dA0, gW + k0);
            CP16(bb + dA1, gW + (size_t)64 * NC + k0);
        }
        CP_COMMIT();

        int st = c % 3;
        uint32_t aB = smbase + (uint32_t)(st * 2 * CHUNK_HALFS) * 2;
        uint32_t bB = aB + CHUNK_HALFS * 2;
#pragma unroll
        for (int ks = 0; ks < 2; ks++) {
            int k0 = ks * 16;
            uint32_t af[4][4], bf[4][2];
#pragma unroll
            for (int mt = 0; mt < 4; mt++) {
                uint32_t addr = aB + (uint32_t)(((wr * 64 + mt * 16 + a_row) * KH + k0 + a_col) * 2);
                LDSM_X4(af[mt][0], af[mt][1], af[mt][2], af[mt][3], addr);
            }
#pragma unroll
            for (int j = 0; j < 2; j++) {
                uint32_t addr = bB + (uint32_t)(((wc * 32 + j * 16 + b_row) * KH + k0 + b_col) * 2);
                LDSM_X4(bf[2 * j][0], bf[2 * j][1], bf[2 * j + 1][0], bf[2 * j + 1][1], addr);
            }
#pragma unroll
            for (int mt = 0; mt < 4; mt++)
#pragma unroll
                for (int nt = 0; nt < 4; nt++)
                    mma_f16(acc[mt][nt], af[mt], bf[nt]);
        }
    }

    // -------------------------- epilogue --------------------------
    int colw = col0 + wc * 32;
    float bv[4][2];
#pragma unroll
    for (int nt = 0; nt < 4; nt++) {
        bv[nt][0] = bias[colw + nt * 8 + 2 * lc];
        bv[nt][1] = bias[colw + nt * 8 + 2 * lc + 1];
    }

    if (mode == 0) {
        int which = colw >> 9;
        int head = (colw & 511) >> 5;
#pragma unroll
        for (int mt = 0; mt < 4; mt++) {
            int gr0 = row0 + wr * 64 + mt * 16 + lr;
            int bi = gr0 >> 8;
            int n0i = gr0 & 255, n1i = n0i + 8;
            int bh = bi * NH + head;
#pragma unroll
            for (int nt = 0; nt < 4; nt++) {
                int d = nt * 8 + 2 * lc;
                float v00 = acc[mt][nt][0] + bv[nt][0];
                float v01 = acc[mt][nt][1] + bv[nt][1];
                float v10 = acc[mt][nt][2] + bv[nt][0];
                float v11 = acc[mt][nt][3] + bv[nt][1];
                if (which == 0) {
                    float qs = QSCALE * LOG2E;
                    __half* p = g_Qh + ((size_t)bh * NN) * HD;
                    *(uint32_t*)(p + (size_t)n0i * HD + d) = ph2(v00 * qs, v01 * qs);
                    *(uint32_t*)(p + (size_t)n1i * HD + d) = ph2(v10 * qs, v11 * qs);
                } else if (which == 1) {
                    __half* p = g_Kh + ((size_t)bh * NN) * HD;
                    *(uint32_t*)(p + (size_t)n0i * HD + d) = ph2(v00, v01);
                    *(uint32_t*)(p + (size_t)n1i * HD + d) = ph2(v10, v11);
                } else {
                    __half* p = g_Vh + ((size_t)bh * HD) * NN;   // [dim][key]
                    p[(size_t)d * NN + n0i]       = __float2half_rn(v00);
                    p[(size_t)(d + 1) * NN + n0i] = __float2half_rn(v01);
                    p[(size_t)d * NN + n1i]       = __float2half_rn(v10);
                    p[(size_t)(d + 1) * NN + n1i] = __float2half_rn(v11);
                }
            }
        }
    } else {
#pragma unroll
        for (int mt = 0; mt < 4; mt++) {
            int gr0 = row0 + wr * 64 + mt * 16 + lr;
            float* p0 = out + (size_t)gr0 * NC + colw;
            float* p1 = out + (size_t)(gr0 + 8) * NC + colw;
#pragma unroll
            for (int nt = 0; nt < 4; nt++) {
                int d = nt * 8 + 2 * lc;
                *(float2*)(p0 + d) = make_float2(acc[mt][nt][0] + bv[nt][0],
                                                 acc[mt][nt][1] + bv[nt][1]);
                *(float2*)(p1 + d) = make_float2(acc[mt][nt][2] + bv[nt][0],
                                                 acc[mt][nt][3] + bv[nt][1]);
            }
        }
    }
}

// ---------------------------------------------------------------------------
// fp16 attention, max-free softmax, ldmatrix fragment loads for K and V.
// ---------------------------------------------------------------------------
__global__ __launch_bounds__(256, 2) void attn_mma() {
    extern __shared__ __half smh[];
    __half* Ks = smh;
    __half* Vs = smh + NN * KS_ST;
    int tid = threadIdx.x;
    int w = tid >> 5, lane = tid & 31;
    int lr = lane >> 2, lc = lane & 3;
    int b_row = ((lane >> 4) << 3) + (lane & 7);
    int b_col = ((lane >> 3) & 1) * 8;

    uint32_t KsB = (uint32_t)__cvta_generic_to_shared(Ks);
    uint32_t VsB = (uint32_t)__cvta_generic_to_shared(Vs);

    int bh = blockIdx.x;
    int b = bh >> 4, h = bh & 15;
    size_t baseq = (size_t)bh * NN * HD;

#pragma unroll
    for (int i = 0; i < 4; i++) {
        int idx = tid + i * 256;
        int row = idx >> 2, seg = idx & 3;
        *(uint4*)(Ks + row * KS_ST + seg * 8) =
            *(const uint4*)(g_Kh + baseq + (size_t)row * HD + seg * 8);
    }
#pragma unroll
    for (int i = 0; i < 4; i++) {
        int idx = tid + i * 256;
        int dim = idx >> 5, seg = idx & 31;
        *(uint4*)(Vs + dim * VS_ST + seg * 8) =
            *(const uint4*)(g_Vh + baseq + (size_t)dim * NN + seg * 8);
    }

    // Q fragments
    int m0 = w * 32;
    uint32_t ah[2][2][4];
    const __half* Qb = g_Qh + baseq;
#pragma unroll
    for (int mt = 0; mt < 2; mt++)
#pragma unroll
        for (int kt = 0; kt < 2; kt++) {
            int r0 = m0 + mt * 16 + lr;
            int d0 = kt * 16 + 2 * lc;
            ah[mt][kt][0] = *(const uint32_t*)(Qb + (size_t)r0 * HD + d0);
            ah[mt][kt][1] = *(const uint32_t*)(Qb + (size_t)(r0 + 8) * HD + d0);
            ah[mt][kt][2] = *(const uint32_t*)(Qb + (size_t)r0 * HD + d0 + 8);
            ah[mt][kt][3] = *(const uint32_t*)(Qb + (size_t)(r0 + 8) * HD + d0 + 8);
        }
    __syncthreads();

    const __half* bT = g_biasTh + (size_t)h * NN * NN;

    float l[4] = {0.f, 0.f, 0.f, 0.f};
    float oacc[2][4][4];
#pragma unroll
    for (int mt = 0; mt < 2; mt++)
#pragma unroll
        for (int nt = 0; nt < 4; nt++)
#pragma unroll
            for (int k = 0; k < 4; k++) oacc[mt][nt][k] = 0.0f;

#pragma unroll 1
    for (int nb = 0; nb < 4; nb++) {
        int n0b = nb * 64;
        float sacc[2][8][4];
#pragma unroll
        for (int mt = 0; mt < 2; mt++)
#pragma unroll
            for (int nt = 0; nt < 8; nt++)
#pragma unroll
                for (int k = 0; k < 4; k++) sacc[mt][nt][k] = 0.0f;

        // --- QK^T: ldmatrix B-fragments from K [key][dim] ---
#pragma unroll
        for (int j = 0; j < 4; j++) {        // key pair-tiles (16 keys each)
#pragma unroll
            for (int kt = 0; kt < 2; kt++) { // 16-dim halves
                uint32_t bf0[2], bf1[2];
                uint32_t addr = KsB +
                    (uint32_t)(((n0b + j * 16 + b_row) * KS_ST + kt * 16 + b_col) * 2);
                LDSM_X4(bf0[0], bf0[1], bf1[0], bf1[1], addr);
                mma_f16(sacc[0][2 * j],     ah[0][kt], bf0);
                mma_f16(sacc[1][2 * j],     ah[1][kt], bf0);
                mma_f16(sacc[0][2 * j + 1], ah[0][kt], bf1);
                mma_f16(sacc[1][2 * j + 1], ah[1][kt], bf1);
            }
        }

        // --- p = exp2(s + bias); lane-local l ---
#pragma unroll
        for (int mt = 0; mt < 2; mt++) {
            int r0 = m0 + mt * 16 + lr;
#pragma unroll
            for (int nt = 0; nt < 8; nt++) {
                int n = n0b + nt * 8 + 2 * lc;
                float2 b0 = __half22float2(*(const __half2*)(bT + (size_t)r0 * NN + n));
                float2 b1 = __half22float2(*(const __half2*)(bT + (size_t)(r0 + 8) * NN + n));
                float p0 = exp2f(sacc[mt][nt][0] + b0.x);
                float p1 = exp2f(sacc[mt][nt][1] + b0.y);
                float p2 = exp2f(sacc[mt][nt][2] + b1.x);
                float p3 = exp2f(sacc[mt][nt][3] + b1.y);
                sacc[mt][nt][0] = p0; sacc[mt][nt][1] = p1;
                sacc[mt][nt][2] = p2; sacc[mt][nt][3] = p3;
                l[mt * 2]     += p0 + p1;
                l[mt * 2 + 1] += p2 + p3;
            }
        }

        // --- P·V: ldmatrix B-fragments from V [dim][key] ---
#pragma unroll
        for (int kt = 0; kt < 4; kt++) {     // 16-key chunks
            uint32_t phf[2][4];
#pragma unroll
            for (int mt = 0; mt < 2; mt++) {
                const float* s0 = sacc[mt][2 * kt];
                const float* s1 = sacc[mt][2 * kt + 1];
                phf[mt][0] = ph2(s0[0], s0[1]);
                phf[mt][1] = ph2(s0[2], s0[3]);
                phf[mt][2] = ph2(s1[0], s1[1]);
                phf[mt][3] = ph2(s1[2], s1[3]);
            }
#pragma unroll
            for (int j = 0; j < 2; j++) {    // dim pair-tiles (16 dims each)
                uint32_t vf0[2], vf1[2];
                uint32_t addr = VsB +
                    (uint32_t)(((j * 16 + b_row) * VS_ST + n0b + kt * 16 + b_col) * 2);
                LDSM_X4(vf0[0], vf0[1], vf1[0], vf1[1], addr);
                mma_f16(oacc[0][2 * j],     phf[0], vf0);
                mma_f16(oacc[1][2 * j],     phf[1], vf0);
                mma_f16(oacc[0][2 * j + 1], phf[0], vf1);
                mma_f16(oacc[1][2 * j + 1], phf[1], vf1);
            }
        }
    }

    // --- single row-sum reduction ---
#pragma unroll
    for (int r = 0; r < 4; r++) {
        l[r] += __shfl_xor_sync(0xffffffffu, l[r], 1);
        l[r] += __shfl_xor_sync(0xffffffffu, l[r], 2);
    }

    // epilogue: normalize, write g_AOh fp16
    __half* AObase = g_AOh + (size_t)b * NN * NC + h * HD;
#pragma unroll
    for (int mt = 0; mt < 2; mt++) {
        int r0 = m0 + mt * 16 + lr;
        float inv0 = 1.0f / l[mt * 2];
        float inv1 = 1.0f / l[mt * 2 + 1];
#pragma unroll
        for (int nt = 0; nt < 4; nt++) {
            int d = nt * 8 + 2 * lc;
            *(uint32_t*)(AObase + (size_t)r0 * NC + d) =
                ph2(oacc[mt][nt][0] * inv0, oacc[mt][nt][1] * inv0);
            *(uint32_t*)(AObase + (size_t)(r0 + 8) * NC + d) =
                ph2(oacc[mt][nt][2] * inv1, oacc[mt][nt][3] * inv1);
        }
    }
}

// ---------------------------------------------------------------------------
extern "C" void kernel_launch(void* const* d_in, const int* in_sizes, int n_in,
                              void* d_out, int out_size) {
    const float* x      = (const float*)d_in[0];
    const float* qkv_w  = (const float*)d_in[2];
    const float* qkv_b  = (const float*)d_in[3];
    const float* proj_w = (const float*)d_in[4];
    const float* proj_b = (const float*)d_in[5];
    const float* rpb    = (const float*)d_in[6];
    float* out = (float*)d_out;

    bias_kernel<<<(NH * NN * NN) / 256, 256>>>(rpb);

    int totn4 = XN4 + WQN4 + WPN4;
    f2h3_kernel<<<(totn4 + 255) / 256, 256>>>((const float4*)x,
                                              (const float4*)qkv_w,
                                              (const float4*)proj_w);

    __half* xh;  cudaGetSymbolAddress((void**)&xh,  g_Xh);
    __half* wqh; cudaGetSymbolAddress((void**)&wqh, g_Wqh);
    __half* wph; cudaGetSymbolAddress((void**)&wph, g_Wph);
    __half* aoh; cudaGetSymbolAddress((void**)&aoh, g_AOh);

    cudaFuncSetAttribute(mma_gemm, cudaFuncAttributeMaxDynamicSharedMemorySize, GEMM_SMEM);

    mma_gemm<<<dim3(1536 / BN, (NB * NN) / BM), 256, GEMM_SMEM>>>(xh, wqh, qkv_b, 0, nullptr);

    cudaFuncSetAttribute(attn_mma, cudaFuncAttributeMaxDynamicSharedMemorySize, ATT_SMEM);
    attn_mma<<<NB * NH, 256, ATT_SMEM>>>();

    mma_gemm<<<dim3(NC / BN, (NB * NN) / BM), 256, GEMM_SMEM>>>(aoh, wph, proj_b, 1, out);
}

// round 17
// speedup vs baseline: 1.0690x; 1.0690x over previous
#include <cuda_runtime.h>
#include <cuda_fp16.h>
#include <cstdint>
#include <math.h>

// Shapes (fixed)
#define NB 128
#define NN 256
#define NC 512
#define NH 16
#define HD 32
#define QSCALE 0.17677669529663687f  // 1/sqrt(32)
#define LOG2E  1.4426950408889634f

// GEMM tiling (fp16 k16), 256 threads, 8 warps (2x4), warp tile 64x32
#define BM 128
#define BN 128
#define BK 32
#define KH 40
#define CHUNK_HALFS (BM * KH)
#define STAGES 3
#define GEMM_SMEM (STAGES * 2 * CHUNK_HALFS * 2)   // 61440 B

// Attention smem (halves)
#define KS_ST 40
#define VS_ST 264
#define ATT_SMEM ((NN * KS_ST + HD * VS_ST) * 2)   // 37376 B

// Scratch (device globals — no allocation allowed)
__device__ __half g_Qh[(size_t)NB * NH * NN * HD];  // fp16, scaled QSCALE*LOG2E
__device__ __half g_Kh[(size_t)NB * NH * NN * HD];  // [bh][key][dim]
__device__ __half g_Vh[(size_t)NB * NH * NN * HD];  // [bh][dim][key]
__device__ __half g_biasP[(size_t)NH * 8 * 4 * 2048]; // fragment-ordered bias (2MB)
__device__ __half g_AOh[(size_t)NB * NN * NC];      // attention out, fp16
__device__ __half g_Xh [(size_t)NB * NN * NC];
__device__ __half g_Wqh[(size_t)3 * NC * NC];
__device__ __half g_Wph[(size_t)NC * NC];

__device__ __forceinline__ uint32_t ph2(float a, float b) {
    __half2 h = __floats2half2_rn(a, b);
    return *(uint32_t*)&h;
}
__device__ __forceinline__ void mma_f16(float* d, const uint32_t* a, const uint32_t* b) {
    asm volatile(
        "mma.sync.aligned.m16n8k16.row.col.f32.f16.f16.f32 "
        "{%0,%1,%2,%3}, {%4,%5,%6,%7}, {%8,%9}, {%0,%1,%2,%3};"
        : "+f"(d[0]), "+f"(d[1]), "+f"(d[2]), "+f"(d[3])
        : "r"(a[0]), "r"(a[1]), "r"(a[2]), "r"(a[3]), "r"(b[0]), "r"(b[1]));
}
#define LDSM_X4(r0, r1, r2, r3, addr)                                         \
    asm volatile("ldmatrix.sync.aligned.m8n8.x4.shared.b16 {%0,%1,%2,%3}, [%4];" \
                 : "=r"(r0), "=r"(r1), "=r"(r2), "=r"(r3) : "r"(addr))
#define CP16(dst_u32, src_ptr)                                                \
    asm volatile("cp.async.cg.shared.global [%0], [%1], 16;"                  \
                 :: "r"(dst_u32), "l"(src_ptr))
#define CP_COMMIT() asm volatile("cp.async.commit_group;")
#define CP_WAIT1()  asm volatile("cp.async.wait_group 1;" ::: "memory")

// ---------------------------------------------------------------------------
// Fused fp32->fp16 convert for the three input arrays (one launch)
// ---------------------------------------------------------------------------
#define XN4   (NB * NN * NC / 4)
#define WQN4  (3 * NC * NC / 4)
#define WPN4  (NC * NC / 4)
__global__ void f2h3_kernel(const float4* __restrict__ sx,
                            const float4* __restrict__ swq,
                            const float4* __restrict__ swp) {
    int i = blockIdx.x * blockDim.x + threadIdx.x;
    const float4* src;
    uint2* dst;
    int j;
    if (i < XN4) {
        src = sx; dst = (uint2*)g_Xh; j = i;
    } else if (i < XN4 + WQN4) {
        src = swq; dst = (uint2*)g_Wqh; j = i - XN4;
    } else if (i < XN4 + WQN4 + WPN4) {
        src = swp; dst = (uint2*)g_Wph; j = i - XN4 - WQN4;
    } else {
        return;
    }
    float4 f = src[j];
    dst[j] = make_uint2(ph2(f.x, f.y), ph2(f.z, f.w));
}

// ---------------------------------------------------------------------------
// Bias precompute, fragment-ordered:
// g_biasP[((h*8+w)*4+nb)*2048 + (step*32+lane)*8 + q]
//   step = mt*4+ntp, q: nt = ntp*2+(q>>2), j = q&3
//   m = w*32 + mt*16 + (j>>1)*8 + lr,  n = nb*64 + nt*8 + 2*lc + (j&1)
// ---------------------------------------------------------------------------
__global__ void bias_kernel(const float* __restrict__ rpb) {
    int idx = blockIdx.x * blockDim.x + threadIdx.x;   // 0..1048575
    int q    = idx & 7;
    int lane = (idx >> 3) & 31;
    int step = (idx >> 8) & 7;
    int nb   = (idx >> 11) & 3;
    int w    = (idx >> 13) & 7;
    int h    = idx >> 16;
    int mt = step >> 2, ntp = step & 3;
    int nt = ntp * 2 + (q >> 2);
    int j  = q & 3;
    int lr = lane >> 2, lc = lane & 3;
    int m = w * 32 + mt * 16 + (j >> 1) * 8 + lr;
    int n = nb * 64 + nt * 8 + 2 * lc + (j & 1);
    int t = ((m >> 5) - (n >> 5) + 7) * 63 + ((m & 31) - (n & 31) + 31);
    g_biasP[idx] = __float2half_rn(rpb[t * NH + h] * LOG2E);
}

// ---------------------------------------------------------------------------
// fp16 GEMM: cp.async 3-stage + ldmatrix (unchanged).
// ---------------------------------------------------------------------------
__global__ __launch_bounds__(256, 2) void mma_gemm(const __half* __restrict__ A,
                                                   const __half* __restrict__ W,
                                                   const float* __restrict__ bias,
                                                   int mode, float* __restrict__ out) {
    extern __shared__ __half smh[];
    int tid = threadIdx.x;
    int wid = tid >> 5;
    int lane = tid & 31;
    int wr = wid >> 2;
    int wc = wid & 3;
    int lr = lane >> 2;
    int lc = lane & 3;

    int row0 = blockIdx.y * BM;
    int col0 = blockIdx.x * BN;
    uint32_t smbase = (uint32_t)__cvta_generic_to_shared(smh);

    int rA = tid >> 2, sg = tid & 3;
    const __half* gA = A + (size_t)(row0 + rA) * NC + sg * 8;
    const __half* gW = W + (size_t)(col0 + rA) * NC + sg * 8;
    uint32_t dA0 = (uint32_t)((rA * KH + sg * 8) * 2);
    uint32_t dA1 = (uint32_t)(((rA + 64) * KH + sg * 8) * 2);

    float acc[4][4][4];
#pragma unroll
    for (int i = 0; i < 4; i++)
#pragma unroll
        for (int j = 0; j < 4; j++)
#pragma unroll
            for (int k = 0; k < 4; k++) acc[i][j][k] = 0.0f;

    const int NCH = NC / BK;  // 16
#pragma unroll
    for (int c = 0; c < 2; c++) {
        uint32_t ab = smbase + (uint32_t)(c * 2 * CHUNK_HALFS) * 2;
        uint32_t bb = ab + CHUNK_HALFS * 2;
        CP16(ab + dA0, gA + c * BK);
        CP16(ab + dA1, gA + (size_t)64 * NC + c * BK);
        CP16(bb + dA0, gW + c * BK);
        CP16(bb + dA1, gW + (size_t)64 * NC + c * BK);
        CP_COMMIT();
    }

    int a_row = (lane & 15);
    int a_col = (lane >> 4) * 8;
    int b_row = ((lane >> 4) << 3) + (lane & 7);
    int b_col = ((lane >> 3) & 1) * 8;

#pragma unroll 1
    for (int c = 0; c < NCH; c++) {
        CP_WAIT1();
        __syncthreads();
        if (c + 2 < NCH) {
            int st = (c + 2) % 3;
            uint32_t ab = smbase + (uint32_t)(st * 2 * CHUNK_HALFS) * 2;
            uint32_t bb = ab + CHUNK_HALFS * 2;
            int k0 = (c + 2) * BK;
            CP16(ab + dA0, gA + k0);
            CP16(ab + dA1, gA + (size_t)64 * NC + k0);
            CP16(bb + dA0, gW + k0);
            CP16(bb + dA1, gW + (size_t)64 * NC + k0);
        }
        CP_COMMIT();

        int st = c % 3;
        uint32_t aB = smbase + (uint32_t)(st * 2 * CHUNK_HALFS) * 2;
        uint32_t bB = aB + CHUNK_HALFS * 2;
#pragma unroll
        for (int ks = 0; ks < 2; ks++) {
            int k0 = ks * 16;
            uint32_t af[4][4], bf[4][2];
#pragma unroll
            for (int mt = 0; mt < 4; mt++) {
                uint32_t addr = aB + (uint32_t)(((wr * 64 + mt * 16 + a_row) * KH + k0 + a_col) * 2);
                LDSM_X4(af[mt][0], af[mt][1], af[mt][2], af[mt][3], addr);
            }
#pragma unroll
            for (int j = 0; j < 2; j++) {
                uint32_t addr = bB + (uint32_t)(((wc * 32 + j * 16 + b_row) * KH + k0 + b_col) * 2);
                LDSM_X4(bf[2 * j][0], bf[2 * j][1], bf[2 * j + 1][0], bf[2 * j + 1][1], addr);
            }
#pragma unroll
            for (int mt = 0; mt < 4; mt++)
#pragma unroll
                for (int nt = 0; nt < 4; nt++)
                    mma_f16(acc[mt][nt], af[mt], bf[nt]);
        }
    }

    // -------------------------- epilogue --------------------------
    int colw = col0 + wc * 32;
    float bv[4][2];
#pragma unroll
    for (int nt = 0; nt < 4; nt++) {
        bv[nt][0] = bias[colw + nt * 8 + 2 * lc];
        bv[nt][1] = bias[colw + nt * 8 + 2 * lc + 1];
    }

    if (mode == 0) {
        int which = colw >> 9;
        int head = (colw & 511) >> 5;
#pragma unroll
        for (int mt = 0; mt < 4; mt++) {
            int gr0 = row0 + wr * 64 + mt * 16 + lr;
            int bi = gr0 >> 8;
            int n0i = gr0 & 255, n1i = n0i + 8;
            int bh = bi * NH + head;
#pragma unroll
            for (int nt = 0; nt < 4; nt++) {
                int d = nt * 8 + 2 * lc;
                float v00 = acc[mt][nt][0] + bv[nt][0];
                float v01 = acc[mt][nt][1] + bv[nt][1];
                float v10 = acc[mt][nt][2] + bv[nt][0];
                float v11 = acc[mt][nt][3] + bv[nt][1];
                if (which == 0) {
                    float qs = QSCALE * LOG2E;
                    __half* p = g_Qh + ((size_t)bh * NN) * HD;
                    *(uint32_t*)(p + (size_t)n0i * HD + d) = ph2(v00 * qs, v01 * qs);
                    *(uint32_t*)(p + (size_t)n1i * HD + d) = ph2(v10 * qs, v11 * qs);
                } else if (which == 1) {
                    __half* p = g_Kh + ((size_t)bh * NN) * HD;
                    *(uint32_t*)(p + (size_t)n0i * HD + d) = ph2(v00, v01);
                    *(uint32_t*)(p + (size_t)n1i * HD + d) = ph2(v10, v11);
                } else {
                    __half* p = g_Vh + ((size_t)bh * HD) * NN;   // [dim][key]
                    p[(size_t)d * NN + n0i]       = __float2half_rn(v00);
                    p[(size_t)(d + 1) * NN + n0i] = __float2half_rn(v01);
                    p[(size_t)d * NN + n1i]       = __float2half_rn(v10);
                    p[(size_t)(d + 1) * NN + n1i] = __float2half_rn(v11);
                }
            }
        }
    } else {
#pragma unroll
        for (int mt = 0; mt < 4; mt++) {
            int gr0 = row0 + wr * 64 + mt * 16 + lr;
            float* p0 = out + (size_t)gr0 * NC + colw;
            float* p1 = out + (size_t)(gr0 + 8) * NC + colw;
#pragma unroll
            for (int nt = 0; nt < 4; nt++) {
                int d = nt * 8 + 2 * lc;
                *(float2*)(p0 + d) = make_float2(acc[mt][nt][0] + bv[nt][0],
                                                 acc[mt][nt][1] + bv[nt][1]);
                *(float2*)(p1 + d) = make_float2(acc[mt][nt][2] + bv[nt][0],
                                                 acc[mt][nt][3] + bv[nt][1]);
            }
        }
    }
}

// ---------------------------------------------------------------------------
// fp16 attention, max-free softmax, ldmatrix K/V, fragment-ordered bias.
// ---------------------------------------------------------------------------
__global__ __launch_bounds__(256, 2) void attn_mma() {
    extern __shared__ __half smh[];
    __half* Ks = smh;
    __half* Vs = smh + NN * KS_ST;
    int tid = threadIdx.x;
    int w = tid >> 5, lane = tid & 31;
    int lr = lane >> 2, lc = lane & 3;
    int b_row = ((lane >> 4) << 3) + (lane & 7);
    int b_col = ((lane >> 3) & 1) * 8;

    uint32_t KsB = (uint32_t)__cvta_generic_to_shared(Ks);
    uint32_t VsB = (uint32_t)__cvta_generic_to_shared(Vs);

    int bh = blockIdx.x;
    int b = bh >> 4, h = bh & 15;
    size_t baseq = (size_t)bh * NN * HD;

#pragma unroll
    for (int i = 0; i < 4; i++) {
        int idx = tid + i * 256;
        int row = idx >> 2, seg = idx & 3;
        *(uint4*)(Ks + row * KS_ST + seg * 8) =
            *(const uint4*)(g_Kh + baseq + (size_t)row * HD + seg * 8);
    }
#pragma unroll
    for (int i = 0; i < 4; i++) {
        int idx = tid + i * 256;
        int dim = idx >> 5, seg = idx & 31;
        *(uint4*)(Vs + dim * VS_ST + seg * 8) =
            *(const uint4*)(g_Vh + baseq + (size_t)dim * NN + seg * 8);
    }

    // Q fragments
    int m0 = w * 32;
    uint32_t ah[2][2][4];
    const __half* Qb = g_Qh + baseq;
#pragma unroll
    for (int mt = 0; mt < 2; mt++)
#pragma unroll
        for (int kt = 0; kt < 2; kt++) {
            int r0 = m0 + mt * 16 + lr;
            int d0 = kt * 16 + 2 * lc;
            ah[mt][kt][0] = *(const uint32_t*)(Qb + (size_t)r0 * HD + d0);
            ah[mt][kt][1] = *(const uint32_t*)(Qb + (size_t)(r0 + 8) * HD + d0);
            ah[mt][kt][2] = *(const uint32_t*)(Qb + (size_t)r0 * HD + d0 + 8);
            ah[mt][kt][3] = *(const uint32_t*)(Qb + (size_t)(r0 + 8) * HD + d0 + 8);
        }
    __syncthreads();

    // fragment-ordered bias base for (h, w)
    const __half* bP = g_biasP + ((size_t)(h * 8 + w) * 4) * 2048;

    float l[4] = {0.f, 0.f, 0.f, 0.f};
    float oacc[2][4][4];
#pragma unroll
    for (int mt = 0; mt < 2; mt++)
#pragma unroll
        for (int nt = 0; nt < 4; nt++)
#pragma unroll
            for (int k = 0; k < 4; k++) oacc[mt][nt][k] = 0.0f;

#pragma unroll 1
    for (int nb = 0; nb < 4; nb++) {
        int n0b = nb * 64;
        float sacc[2][8][4];
#pragma unroll
        for (int mt = 0; mt < 2; mt++)
#pragma unroll
            for (int nt = 0; nt < 8; nt++)
#pragma unroll
                for (int k = 0; k < 4; k++) sacc[mt][nt][k] = 0.0f;

        // --- QK^T: ldmatrix B-fragments from K [key][dim] ---
#pragma unroll
        for (int j = 0; j < 4; j++) {
#pragma unroll
            for (int kt = 0; kt < 2; kt++) {
                uint32_t bf0[2], bf1[2];
                uint32_t addr = KsB +
                    (uint32_t)(((n0b + j * 16 + b_row) * KS_ST + kt * 16 + b_col) * 2);
                LDSM_X4(bf0[0], bf0[1], bf1[0], bf1[1], addr);
                mma_f16(sacc[0][2 * j],     ah[0][kt], bf0);
                mma_f16(sacc[1][2 * j],     ah[1][kt], bf0);
                mma_f16(sacc[0][2 * j + 1], ah[0][kt], bf1);
                mma_f16(sacc[1][2 * j + 1], ah[1][kt], bf1);
            }
        }

        // --- p = exp2(s + bias), coalesced LDG.128 bias in fragment order ---
        const __half* bnb = bP + nb * 2048;
#pragma unroll
        for (int mt = 0; mt < 2; mt++) {
#pragma unroll
            for (int ntp = 0; ntp < 4; ntp++) {
                int step = mt * 4 + ntp;
                uint4 u = *(const uint4*)(bnb + (step * 32 + lane) * 8);
                const __half2* hp = (const __half2*)&u;
                float2 c0 = __half22float2(hp[0]);   // nt=2ntp  j0,j1
                float2 c1 = __half22float2(hp[1]);   // nt=2ntp  j2,j3
                float2 c2 = __half22float2(hp[2]);   // nt=2ntp+1 j0,j1
                float2 c3 = __half22float2(hp[3]);   // nt=2ntp+1 j2,j3
                int n0 = 2 * ntp, n1 = 2 * ntp + 1;
                float p0 = exp2f(sacc[mt][n0][0] + c0.x);
                float p1 = exp2f(sacc[mt][n0][1] + c0.y);
                float p2 = exp2f(sacc[mt][n0][2] + c1.x);
                float p3 = exp2f(sacc[mt][n0][3] + c1.y);
                float p4 = exp2f(sacc[mt][n1][0] + c2.x);
                float p5 = exp2f(sacc[mt][n1][1] + c2.y);
                float p6 = exp2f(sacc[mt][n1][2] + c3.x);
                float p7 = exp2f(sacc[mt][n1][3] + c3.y);
                sacc[mt][n0][0] = p0; sacc[mt][n0][1] = p1;
                sacc[mt][n0][2] = p2; sacc[mt][n0][3] = p3;
                sacc[mt][n1][0] = p4; sacc[mt][n1][1] = p5;
                sacc[mt][n1][2] = p6; sacc[mt][n1][3] = p7;
                l[mt * 2]     += p0 + p1 + p4 + p5;
                l[mt * 2 + 1] += p2 + p3 + p6 + p7;
            }
        }

        // --- P·V: ldmatrix B-fragments from V [dim][key] ---
#pragma unroll
        for (int kt = 0; kt < 4; kt++) {
            uint32_t phf[2][4];
#pragma unroll
            for (int mt = 0; mt < 2; mt++) {
                const float* s0 = sacc[mt][2 * kt];
                const float* s1 = sacc[mt][2 * kt + 1];
                phf[mt][0] = ph2(s0[0], s0[1]);
                phf[mt][1] = ph2(s0[2], s0[3]);
                phf[mt][2] = ph2(s1[0], s1[1]);
                phf[mt][3] = ph2(s1[2], s1[3]);
            }
#pragma unroll
            for (int j = 0; j < 2; j++) {
                uint32_t vf0[2], vf1[2];
                uint32_t addr = VsB +
                    (uint32_t)(((j * 16 + b_row) * VS_ST + n0b + kt * 16 + b_col) * 2);
                LDSM_X4(vf0[0], vf0[1], vf1[0], vf1[1], addr);
                mma_f16(oacc[0][2 * j],     phf[0], vf0);
                mma_f16(oacc[1][2 * j],     phf[1], vf0);
                mma_f16(oacc[0][2 * j + 1], phf[0], vf1);
                mma_f16(oacc[1][2 * j + 1], phf[1], vf1);
            }
        }
    }

    // --- single row-sum reduction ---
#pragma unroll
    for (int r = 0; r < 4; r++) {
        l[r] += __shfl_xor_sync(0xffffffffu, l[r], 1);
        l[r] += __shfl_xor_sync(0xffffffffu, l[r], 2);
    }

    // epilogue: normalize, write g_AOh fp16
    __half* AObase = g_AOh + (size_t)b * NN * NC + h * HD;
#pragma unroll
    for (int mt = 0; mt < 2; mt++) {
        int r0 = m0 + mt * 16 + lr;
        float inv0 = 1.0f / l[mt * 2];
        float inv1 = 1.0f / l[mt * 2 + 1];
#pragma unroll
        for (int nt = 0; nt < 4; nt++) {
            int d = nt * 8 + 2 * lc;
            *(uint32_t*)(AObase + (size_t)r0 * NC + d) =
                ph2(oacc[mt][nt][0] * inv0, oacc[mt][nt][1] * inv0);
            *(uint32_t*)(AObase + (size_t)(r0 + 8) * NC + d) =
                ph2(oacc[mt][nt][2] * inv1, oacc[mt][nt][3] * inv1);
        }
    }
}

// ---------------------------------------------------------------------------
extern "C" void kernel_launch(void* const* d_in, const int* in_sizes, int n_in,
                              void* d_out, int out_size) {
    const float* x      = (const float*)d_in[0];
    const float* qkv_w  = (const float*)d_in[2];
    const float* qkv_b  = (const float*)d_in[3];
    const float* proj_w = (const float*)d_in[4];
    const float* proj_b = (const float*)d_in[5];
    const float* rpb    = (const float*)d_in[6];
    float* out = (float*)d_out;

    bias_kernel<<<(NH * NN * NN) / 256, 256>>>(rpb);

    int totn4 = XN4 + WQN4 + WPN4;
    f2h3_kernel<<<(totn4 + 255) / 256, 256>>>((const float4*)x,
                                              (const float4*)qkv_w,
                                              (const float4*)proj_w);

    __half* xh;  cudaGetSymbolAddress((void**)&xh,  g_Xh);
    __half* wqh; cudaGetSymbolAddress((void**)&wqh, g_Wqh);
    __half* wph; cudaGetSymbolAddress((void**)&wph, g_Wph);
    __half* aoh; cudaGetSymbolAddress((void**)&aoh, g_AOh);

    cudaFuncSetAttribute(mma_gemm, cudaFuncAttributeMaxDynamicSharedMemorySize, GEMM_SMEM);

    mma_gemm<<<dim3(1536 / BN, (NB * NN) / BM), 256, GEMM_SMEM>>>(xh, wqh, qkv_b, 0, nullptr);

    cudaFuncSetAttribute(attn_mma, cudaFuncAttributeMaxDynamicSharedMemorySize, ATT_SMEM);
    attn_mma<<<NB * NH, 256, ATT_SMEM>>>();

    mma_gemm<<<dim3(NC / BN, (NB * NN) / BM), 256, GEMM_SMEM>>>(aoh, wph, proj_b, 1, out);
}